// round 1
// baseline (speedup 1.0000x reference)
#include <cuda_runtime.h>
#include <math.h>

// Problem constants
#define BB 8
#define HH 256
#define WW2 256
#define CDIM 96
#define NHEAD 4
#define HD 24
#define WS 8
#define NTOK 64
#define SHIFT 4
#define NWIN 8192     // B * 32 * 32
#define NPIX (BB*HH*WW2)

// smem row strides (padded to avoid bank conflicts)
#define YS 97
#define QS 289
#define SS 65
#define TS 385

#define SMEM1 ((64*YS + 64*QS + 64*SS)*4)
#define SMEM2 ((64*YS + 64*YS + 64*TS)*4)

// scratch: x1 = shortcut + attention branch (201 MB)
static __device__ float g_x1[(size_t)BB*HH*WW2*CDIM];

// ---------------------------------------------------------------------------
// Kernel 1: per-window  LN1 + shift + QKV + attention + proj + residual
// ---------------------------------------------------------------------------
__global__ __launch_bounds__(256, 1) void k_attn(
    const float* __restrict__ x,
    const float* __restrict__ n1g, const float* __restrict__ n1b,
    const float* __restrict__ qkvw, const float* __restrict__ qkvb,
    const float* __restrict__ relb,
    const float* __restrict__ pw,  const float* __restrict__ pb)
{
    extern __shared__ float sm[];
    float* sy = sm;              // 64 x YS   (LN'd input; reused as attention output o)
    float* sq = sm + 64*YS;      // 64 x QS   (qkv: q|k|v, 288 cols)
    float* ss = sq + 64*QS;      // 64 x SS   (scores, one head at a time)

    const int t   = threadIdx.x;
    const int win = blockIdx.x;
    const int b   = win >> 10;
    const int wr  = win & 1023;
    const int wh  = wr >> 5;
    const int ww  = wr & 31;

    // ---- LN1 with cyclic-shift gather: 4 lanes per token ----
    {
        const int n = t >> 2, q = t & 3;
        const int i = n >> 3, j = n & 7;
        const int h0 = (wh*8 + i + SHIFT) & 255;
        const int w0 = (ww*8 + j + SHIFT) & 255;
        const float* xp = x + (((size_t)b*HH + h0)*WW2 + w0)*CDIM;
        float v[24];
        float s1 = 0.f, s2 = 0.f;
#pragma unroll
        for (int k = 0; k < 24; k++) {
            float vv = xp[q + 4*k];
            v[k] = vv; s1 += vv; s2 += vv*vv;
        }
        s1 += __shfl_xor_sync(0xffffffffu, s1, 1);
        s2 += __shfl_xor_sync(0xffffffffu, s2, 1);
        s1 += __shfl_xor_sync(0xffffffffu, s1, 2);
        s2 += __shfl_xor_sync(0xffffffffu, s2, 2);
        const float mean = s1 * (1.f/96.f);
        const float var  = s2 * (1.f/96.f) - mean*mean;
        const float rstd = rsqrtf(var + 1e-5f);
#pragma unroll
        for (int k = 0; k < 24; k++) {
            const int c = q + 4*k;
            sy[n*YS + c] = (v[k]-mean)*rstd*n1g[c] + n1b[c];
        }
    }
    __syncthreads();

    const int tx = t & 15, ty = t >> 4;

    // ---- QKV GEMM: (64x96) @ (96x288) + bias -> sq ----
    for (int co0 = 0; co0 < 288; co0 += 64) {
        float acc[4][4];
#pragma unroll
        for (int rr = 0; rr < 4; rr++)
#pragma unroll
            for (int cc = 0; cc < 4; cc++) acc[rr][cc] = 0.f;

#pragma unroll 4
        for (int ci = 0; ci < 96; ci++) {
            float a[4], w[4];
#pragma unroll
            for (int rr = 0; rr < 4; rr++) a[rr] = sy[(ty + 16*rr)*YS + ci];
#pragma unroll
            for (int cc = 0; cc < 4; cc++) {
                const int c = co0 + tx + 16*cc;
                w[cc] = (c < 288) ? qkvw[ci*288 + c] : 0.f;
            }
#pragma unroll
            for (int rr = 0; rr < 4; rr++)
#pragma unroll
                for (int cc = 0; cc < 4; cc++) acc[rr][cc] = fmaf(a[rr], w[cc], acc[rr][cc]);
        }
#pragma unroll
        for (int rr = 0; rr < 4; rr++)
#pragma unroll
            for (int cc = 0; cc < 4; cc++) {
                const int c = co0 + tx + 16*cc;
                if (c < 288) sq[(ty + 16*rr)*QS + c] = acc[rr][cc] + qkvb[c];
            }
    }
    __syncthreads();

    const float SCALE = rsqrtf((float)HD);   // 24^-0.5

    // region id helpers for the shifted-window mask (computed analytically)
    const bool edgeH = (wh == 31), edgeW = (ww == 31);

    // ---- per-head attention ----
    for (int h = 0; h < NHEAD; h++) {
        const int qo = h*HD, ko = 96 + h*HD, vo = 192 + h*HD;

        // scores: s[n1][n2] = clip( q.k*SCALE + mask + clip(bias,-5,5), -10, 10 )
        {
            float acc[4][4];
#pragma unroll
            for (int rr = 0; rr < 4; rr++)
#pragma unroll
                for (int cc = 0; cc < 4; cc++) acc[rr][cc] = 0.f;
#pragma unroll 4
            for (int d = 0; d < HD; d++) {
                float a[4], k2[4];
#pragma unroll
                for (int rr = 0; rr < 4; rr++) a[rr]  = sq[(ty + 16*rr)*QS + qo + d];
#pragma unroll
                for (int cc = 0; cc < 4; cc++) k2[cc] = sq[(tx + 16*cc)*QS + ko + d];
#pragma unroll
                for (int rr = 0; rr < 4; rr++)
#pragma unroll
                    for (int cc = 0; cc < 4; cc++) acc[rr][cc] = fmaf(a[rr], k2[cc], acc[rr][cc]);
            }
#pragma unroll
            for (int rr = 0; rr < 4; rr++) {
                const int n1 = ty + 16*rr;
                const int i1 = n1 >> 3, j1 = n1 & 7;
                const int r1 = (edgeH ? ((i1 < 4) ? 1 : 2) : 0)*3 + (edgeW ? ((j1 < 4) ? 1 : 2) : 0);
#pragma unroll
                for (int cc = 0; cc < 4; cc++) {
                    const int n2 = tx + 16*cc;
                    const int i2 = n2 >> 3, j2 = n2 & 7;
                    const int r2 = (edgeH ? ((i2 < 4) ? 1 : 2) : 0)*3 + (edgeW ? ((j2 < 4) ? 1 : 2) : 0);
                    const int di = i1 - i2 + 7, dj = j1 - j2 + 7;
                    float bias = relb[(di*15 + dj)*NHEAD + h];
                    bias = fminf(fmaxf(bias, -5.f), 5.f);
                    float v = acc[rr][cc]*SCALE + ((r1 == r2) ? 0.f : -1e9f) + bias;
                    v = fminf(fmaxf(v, -10.f), 10.f);
                    ss[n1*SS + n2] = v;
                }
            }
        }
        __syncthreads();

        // softmax per row (4 lanes per row, within one warp)
        {
            const int rn = t >> 2, rq = t & 3;
            float m = -1e30f;
#pragma unroll
            for (int k = 0; k < 16; k++) m = fmaxf(m, ss[rn*SS + rq*16 + k]);
            m = fmaxf(m, __shfl_xor_sync(0xffffffffu, m, 1));
            m = fmaxf(m, __shfl_xor_sync(0xffffffffu, m, 2));
            float sum = 0.f;
#pragma unroll
            for (int k = 0; k < 16; k++) {
                float e = __expf(ss[rn*SS + rq*16 + k] - m);
                ss[rn*SS + rq*16 + k] = e;
                sum += e;
            }
            sum += __shfl_xor_sync(0xffffffffu, sum, 1);
            sum += __shfl_xor_sync(0xffffffffu, sum, 2);
            const float inv = 1.f / sum;
#pragma unroll
            for (int k = 0; k < 16; k++) ss[rn*SS + rq*16 + k] *= inv;
            __syncwarp();
        }

        // AV: o[n][h*24 + d] = sum_j s[n][j] * v[j][d]   (o lives in sy)
        {
            const int dn = t >> 2, dq = t & 3;
            float acc[6];
#pragma unroll
            for (int k = 0; k < 6; k++) acc[k] = 0.f;
#pragma unroll 4
            for (int j = 0; j < 64; j++) {
                const float sv = ss[dn*SS + j];
#pragma unroll
                for (int k = 0; k < 6; k++)
                    acc[k] = fmaf(sv, sq[j*QS + vo + dq*6 + k], acc[k]);
            }
#pragma unroll
            for (int k = 0; k < 6; k++) sy[dn*YS + h*HD + dq*6 + k] = acc[k];
        }
        __syncthreads();
    }

    // ---- proj + un-shift + residual store to g_x1 ----
    for (int co0 = 0; co0 < 96; co0 += 64) {
        float acc[4][4];
#pragma unroll
        for (int rr = 0; rr < 4; rr++)
#pragma unroll
            for (int cc = 0; cc < 4; cc++) acc[rr][cc] = 0.f;
#pragma unroll 4
        for (int k = 0; k < 96; k++) {
            float a[4], w[4];
#pragma unroll
            for (int rr = 0; rr < 4; rr++) a[rr] = sy[(ty + 16*rr)*YS + k];
#pragma unroll
            for (int cc = 0; cc < 4; cc++) {
                const int c = co0 + tx + 16*cc;
                w[cc] = (c < 96) ? pw[k*96 + c] : 0.f;
            }
#pragma unroll
            for (int rr = 0; rr < 4; rr++)
#pragma unroll
                for (int cc = 0; cc < 4; cc++) acc[rr][cc] = fmaf(a[rr], w[cc], acc[rr][cc]);
        }
#pragma unroll
        for (int rr = 0; rr < 4; rr++)
#pragma unroll
            for (int cc = 0; cc < 4; cc++) {
                const int c = co0 + tx + 16*cc;
                if (c < 96) {
                    const int n = ty + 16*rr;
                    const int i = n >> 3, j = n & 7;
                    const int h1 = (wh*8 + i + SHIFT) & 255;
                    const int w1 = (ww*8 + j + SHIFT) & 255;
                    const size_t off = (((size_t)b*HH + h1)*WW2 + w1)*CDIM + c;
                    g_x1[off] = x[off] + acc[rr][cc] + pb[c];
                }
            }
    }
}

// ---------------------------------------------------------------------------
// Kernel 2: per-64-pixel tile  LN2 + MLP (96->384 GELU 384->96) + residual
// ---------------------------------------------------------------------------
__global__ __launch_bounds__(256, 1) void k_mlp(
    const float* __restrict__ n2g, const float* __restrict__ n2b,
    const float* __restrict__ w1,  const float* __restrict__ b1,
    const float* __restrict__ w2,  const float* __restrict__ b2,
    float* __restrict__ out)
{
    extern __shared__ float sm[];
    float* sx = sm;              // 64 x YS  (raw x1, for residual)
    float* sn = sm + 64*YS;      // 64 x YS  (LN'd)
    float* st = sn + 64*YS;      // 64 x TS  (hidden 384, after GELU)

    const int t  = threadIdx.x;
    const size_t p0 = (size_t)blockIdx.x * 64;

    // load 64 consecutive pixels
    for (int e = t; e < 64*96; e += 256)
        sx[(e/96)*YS + (e%96)] = g_x1[p0*CDIM + e];
    __syncthreads();

    // LN2
    {
        const int n = t >> 2, q = t & 3;
        float s1 = 0.f, s2 = 0.f;
        float v[24];
#pragma unroll
        for (int k = 0; k < 24; k++) {
            float vv = sx[n*YS + q + 4*k];
            v[k] = vv; s1 += vv; s2 += vv*vv;
        }
        s1 += __shfl_xor_sync(0xffffffffu, s1, 1);
        s2 += __shfl_xor_sync(0xffffffffu, s2, 1);
        s1 += __shfl_xor_sync(0xffffffffu, s1, 2);
        s2 += __shfl_xor_sync(0xffffffffu, s2, 2);
        const float mean = s1 * (1.f/96.f);
        const float var  = s2 * (1.f/96.f) - mean*mean;
        const float rstd = rsqrtf(var + 1e-5f);
#pragma unroll
        for (int k = 0; k < 24; k++) {
            const int c = q + 4*k;
            sn[n*YS + c] = (v[k]-mean)*rstd*n2g[c] + n2b[c];
        }
    }
    __syncthreads();

    const int tx = t & 15, ty = t >> 4;

    // GEMM1: (64x96)@(96x384) + b1, GELU -> st
    for (int co0 = 0; co0 < 384; co0 += 64) {
        float acc[4][4];
#pragma unroll
        for (int rr = 0; rr < 4; rr++)
#pragma unroll
            for (int cc = 0; cc < 4; cc++) acc[rr][cc] = 0.f;
#pragma unroll 4
        for (int ci = 0; ci < 96; ci++) {
            float a[4], w[4];
#pragma unroll
            for (int rr = 0; rr < 4; rr++) a[rr] = sn[(ty + 16*rr)*YS + ci];
#pragma unroll
            for (int cc = 0; cc < 4; cc++) w[cc] = w1[ci*384 + co0 + tx + 16*cc];
#pragma unroll
            for (int rr = 0; rr < 4; rr++)
#pragma unroll
                for (int cc = 0; cc < 4; cc++) acc[rr][cc] = fmaf(a[rr], w[cc], acc[rr][cc]);
        }
#pragma unroll
        for (int rr = 0; rr < 4; rr++)
#pragma unroll
            for (int cc = 0; cc < 4; cc++) {
                const int c = co0 + tx + 16*cc;
                float v = acc[rr][cc] + b1[c];
                // exact GELU
                v = 0.5f * v * (1.f + erff(v * 0.7071067811865476f));
                st[(ty + 16*rr)*TS + c] = v;
            }
    }
    __syncthreads();

    // GEMM2: (64x384)@(384x96) + b2 + residual -> out
    for (int co0 = 0; co0 < 96; co0 += 64) {
        float acc[4][4];
#pragma unroll
        for (int rr = 0; rr < 4; rr++)
#pragma unroll
            for (int cc = 0; cc < 4; cc++) acc[rr][cc] = 0.f;
#pragma unroll 4
        for (int k = 0; k < 384; k++) {
            float a[4], w[4];
#pragma unroll
            for (int rr = 0; rr < 4; rr++) a[rr] = st[(ty + 16*rr)*TS + k];
#pragma unroll
            for (int cc = 0; cc < 4; cc++) {
                const int c = co0 + tx + 16*cc;
                w[cc] = (c < 96) ? w2[k*96 + c] : 0.f;
            }
#pragma unroll
            for (int rr = 0; rr < 4; rr++)
#pragma unroll
                for (int cc = 0; cc < 4; cc++) acc[rr][cc] = fmaf(a[rr], w[cc], acc[rr][cc]);
        }
#pragma unroll
        for (int rr = 0; rr < 4; rr++)
#pragma unroll
            for (int cc = 0; cc < 4; cc++) {
                const int c = co0 + tx + 16*cc;
                if (c < 96) {
                    const int r = ty + 16*rr;
                    out[(p0 + r)*CDIM + c] = sx[r*YS + c] + acc[rr][cc] + b2[c];
                }
            }
    }
}

// ---------------------------------------------------------------------------
extern "C" void kernel_launch(void* const* d_in, const int* in_sizes, int n_in,
                              void* d_out, int out_size)
{
    const float* x    = (const float*)d_in[0];
    const float* n1g  = (const float*)d_in[1];
    const float* n1b  = (const float*)d_in[2];
    const float* qkvw = (const float*)d_in[3];
    const float* qkvb = (const float*)d_in[4];
    const float* relb = (const float*)d_in[5];
    const float* pw   = (const float*)d_in[6];
    const float* pb   = (const float*)d_in[7];
    const float* n2g  = (const float*)d_in[8];
    const float* n2b  = (const float*)d_in[9];
    const float* w1   = (const float*)d_in[10];
    const float* b1   = (const float*)d_in[11];
    const float* w2   = (const float*)d_in[12];
    const float* b2   = (const float*)d_in[13];
    float* out = (float*)d_out;

    cudaFuncSetAttribute(k_attn, cudaFuncAttributeMaxDynamicSharedMemorySize, SMEM1);
    cudaFuncSetAttribute(k_mlp,  cudaFuncAttributeMaxDynamicSharedMemorySize, SMEM2);

    k_attn<<<NWIN, 256, SMEM1>>>(x, n1g, n1b, qkvw, qkvb, relb, pw, pb);
    k_mlp<<<NPIX/64, 256, SMEM2>>>(n2g, n2b, w1, b1, w2, b2, out);
}

// round 4
// speedup vs baseline: 1.7958x; 1.7958x over previous
#include <cuda_runtime.h>
#include <math.h>

// Problem constants
#define BB 8
#define HH 256
#define WW2 256
#define CDIM 96
#define NHEAD 4
#define HD 24
#define WS 8
#define NTOK 64
#define SHIFT 4
#define NWIN 8192     // B * 32 * 32
#define NPIX (BB*HH*WW2)

// ---- k_attn smem layout (floats) ----
#define YS 97
#define QS 289
#define SS 65
#define SMEM1_FLOATS (64*YS + 64*QS + 900)
#define SMEM1 (SMEM1_FLOATS*4)

// ---- k_mlp smem layout (floats) ----
#define MROWS 128
#define SXS 96
#define SNS 100
#define STS 68
#define SW1S 64
#define SW2S 96
#define SMEM2_FLOATS (MROWS*SXS + MROWS*SNS + MROWS*STS + 96*SW1S + 64*SW2S)
#define SMEM2 (SMEM2_FLOATS*4)

// scratch: x1 = shortcut + attention branch
static __device__ float g_x1[(size_t)BB*HH*WW2*CDIM];

// ---------------------------------------------------------------------------
// Kernel 1: per-window  LN1 + shift + QKV + attention + proj + residual
// ---------------------------------------------------------------------------
__global__ __launch_bounds__(256, 2) void k_attn(
    const float* __restrict__ x,
    const float* __restrict__ n1g, const float* __restrict__ n1b,
    const float* __restrict__ qkvw, const float* __restrict__ qkvb,
    const float* __restrict__ relb,
    const float* __restrict__ pw,  const float* __restrict__ pb)
{
    extern __shared__ float sm[];
    float* sy    = sm;                 // 64 x YS (LN'd; later attn out)
    float* ss    = sm;                 // 64 x SS (scores; aliases sy, disjoint lifetime)
    float* sq    = sm + 64*YS;         // 64 x QS (qkv 288 cols)
    float* sbias = sq + 64*QS;         // 4 x 225 clipped rel-bias LUT

    const int t   = threadIdx.x;
    const int win = blockIdx.x;
    const int b   = win >> 10;
    const int wr  = win & 1023;
    const int wh  = wr >> 5;
    const int ww  = wr & 31;

    // ---- clipped rel-bias LUT ----
    for (int e = t; e < 900; e += 256) {
        const int h = e / 225, idx = e - h*225;
        float bv = relb[idx*NHEAD + h];
        sbias[e] = fminf(fmaxf(bv, -5.f), 5.f);
    }

    // ---- LN1 with cyclic-shift gather: 4 lanes per token ----
    {
        const int n = t >> 2, q = t & 3;
        const int i = n >> 3, j = n & 7;
        const int h0 = (wh*8 + i + SHIFT) & 255;
        const int w0 = (ww*8 + j + SHIFT) & 255;
        const float* xp = x + (((size_t)b*HH + h0)*WW2 + w0)*CDIM;
        float v[24];
        float s1 = 0.f, s2 = 0.f;
#pragma unroll
        for (int k = 0; k < 24; k++) {
            float vv = xp[q + 4*k];
            v[k] = vv; s1 += vv; s2 += vv*vv;
        }
        s1 += __shfl_xor_sync(0xffffffffu, s1, 1);
        s2 += __shfl_xor_sync(0xffffffffu, s2, 1);
        s1 += __shfl_xor_sync(0xffffffffu, s1, 2);
        s2 += __shfl_xor_sync(0xffffffffu, s2, 2);
        const float mean = s1 * (1.f/96.f);
        const float var  = s2 * (1.f/96.f) - mean*mean;
        const float rstd = rsqrtf(var + 1e-5f);
#pragma unroll
        for (int k = 0; k < 24; k++) {
            const int c = q + 4*k;
            sy[n*YS + c] = (v[k]-mean)*rstd*n1g[c] + n1b[c];
        }
    }
    __syncthreads();

    const int tx = t & 15, ty = t >> 4;

    // ---- QKV GEMM: (64x96)@(96x288) + bias -> sq.  3 passes x 96 cols,
    //      per-thread tile 4 rows x 6 cols (16*6 = 96, no guards) ----
    for (int co0 = 0; co0 < 288; co0 += 96) {
        float acc[4][6];
#pragma unroll
        for (int rr = 0; rr < 4; rr++)
#pragma unroll
            for (int cc = 0; cc < 6; cc++) acc[rr][cc] = 0.f;
#pragma unroll 4
        for (int ci = 0; ci < 96; ci++) {
            float a[4], w[6];
#pragma unroll
            for (int rr = 0; rr < 4; rr++) a[rr] = sy[(ty + 16*rr)*YS + ci];
#pragma unroll
            for (int cc = 0; cc < 6; cc++) w[cc] = qkvw[ci*288 + co0 + tx + 16*cc];
#pragma unroll
            for (int rr = 0; rr < 4; rr++)
#pragma unroll
                for (int cc = 0; cc < 6; cc++) acc[rr][cc] = fmaf(a[rr], w[cc], acc[rr][cc]);
        }
#pragma unroll
        for (int rr = 0; rr < 4; rr++)
#pragma unroll
            for (int cc = 0; cc < 6; cc++) {
                const int c = co0 + tx + 16*cc;
                sq[(ty + 16*rr)*QS + c] = acc[rr][cc] + qkvb[c];
            }
    }
    __syncthreads();
    // sy's LN contents are dead from here; ss (scores) reuses that space.

    const float SCALE = rsqrtf((float)HD);
    const bool edgeH = (wh == 31), edgeW = (ww == 31);

    float oreg[NHEAD][6];   // attention output accumulators, in registers

    for (int h = 0; h < NHEAD; h++) {
        const int qo = h*HD, ko = 96 + h*HD, vo = 192 + h*HD;

        // scores (64x64): per-thread 4x4 tile
        {
            float acc[4][4];
#pragma unroll
            for (int rr = 0; rr < 4; rr++)
#pragma unroll
                for (int cc = 0; cc < 4; cc++) acc[rr][cc] = 0.f;
#pragma unroll 4
            for (int d = 0; d < HD; d++) {
                float a[4], k2[4];
#pragma unroll
                for (int rr = 0; rr < 4; rr++) a[rr]  = sq[(ty + 16*rr)*QS + qo + d];
#pragma unroll
                for (int cc = 0; cc < 4; cc++) k2[cc] = sq[(tx + 16*cc)*QS + ko + d];
#pragma unroll
                for (int rr = 0; rr < 4; rr++)
#pragma unroll
                    for (int cc = 0; cc < 4; cc++) acc[rr][cc] = fmaf(a[rr], k2[cc], acc[rr][cc]);
            }
#pragma unroll
            for (int rr = 0; rr < 4; rr++) {
                const int n1 = ty + 16*rr;
                const int i1 = n1 >> 3, j1 = n1 & 7;
                const int r1 = (edgeH ? ((i1 < 4) ? 1 : 2) : 0)*3 + (edgeW ? ((j1 < 4) ? 1 : 2) : 0);
#pragma unroll
                for (int cc = 0; cc < 4; cc++) {
                    const int n2 = tx + 16*cc;
                    const int i2 = n2 >> 3, j2 = n2 & 7;
                    const int r2 = (edgeH ? ((i2 < 4) ? 1 : 2) : 0)*3 + (edgeW ? ((j2 < 4) ? 1 : 2) : 0);
                    const int di = i1 - i2 + 7, dj = j1 - j2 + 7;
                    float bias = sbias[h*225 + di*15 + dj];
                    float v = acc[rr][cc]*SCALE + ((r1 == r2) ? 0.f : -1e9f) + bias;
                    v = fminf(fmaxf(v, -10.f), 10.f);
                    ss[n1*SS + n2] = v;
                }
            }
        }
        __syncthreads();

        // softmax per row (quad of lanes per row, within one warp)
        {
            const int rn = t >> 2, rq = t & 3;
            float m = -1e30f;
#pragma unroll
            for (int k = 0; k < 16; k++) m = fmaxf(m, ss[rn*SS + rq*16 + k]);
            m = fmaxf(m, __shfl_xor_sync(0xffffffffu, m, 1));
            m = fmaxf(m, __shfl_xor_sync(0xffffffffu, m, 2));
            float sum = 0.f;
#pragma unroll
            for (int k = 0; k < 16; k++) {
                float e = __expf(ss[rn*SS + rq*16 + k] - m);
                ss[rn*SS + rq*16 + k] = e;
                sum += e;
            }
            sum += __shfl_xor_sync(0xffffffffu, sum, 1);
            sum += __shfl_xor_sync(0xffffffffu, sum, 2);
            const float inv = 1.f / sum;
#pragma unroll
            for (int k = 0; k < 16; k++) ss[rn*SS + rq*16 + k] *= inv;
            __syncwarp();
        }

        // AV -> registers (thread t: row t>>2, 6 head-dims starting (t&3)*6)
        {
            const int dn = t >> 2, dq = t & 3;
            float acc[6];
#pragma unroll
            for (int k = 0; k < 6; k++) acc[k] = 0.f;
#pragma unroll 4
            for (int j = 0; j < 64; j++) {
                const float sv = ss[dn*SS + j];
#pragma unroll
                for (int k = 0; k < 6; k++)
                    acc[k] = fmaf(sv, sq[j*QS + vo + dq*6 + k], acc[k]);
            }
#pragma unroll
            for (int k = 0; k < 6; k++) oreg[h][k] = acc[k];
        }
        __syncthreads();
    }

    // write o (registers) -> sy, overwriting the dead score buffer
    {
        const int dn = t >> 2, dq = t & 3;
#pragma unroll
        for (int h = 0; h < NHEAD; h++)
#pragma unroll
            for (int k = 0; k < 6; k++)
                sy[dn*YS + h*HD + dq*6 + k] = oreg[h][k];
    }
    __syncthreads();

    // ---- proj (64x96)@(96x96) + un-shift + residual -> g_x1.
    //      per-thread 4 rows x 6 cols: covers all 96 cols, no guards ----
    {
        float acc[4][6];
#pragma unroll
        for (int rr = 0; rr < 4; rr++)
#pragma unroll
            for (int cc = 0; cc < 6; cc++) acc[rr][cc] = 0.f;
#pragma unroll 4
        for (int k = 0; k < 96; k++) {
            float a[4], w[6];
#pragma unroll
            for (int rr = 0; rr < 4; rr++) a[rr] = sy[(ty + 16*rr)*YS + k];
#pragma unroll
            for (int cc = 0; cc < 6; cc++) w[cc] = pw[k*96 + tx + 16*cc];
#pragma unroll
            for (int rr = 0; rr < 4; rr++)
#pragma unroll
                for (int cc = 0; cc < 6; cc++) acc[rr][cc] = fmaf(a[rr], w[cc], acc[rr][cc]);
        }
#pragma unroll
        for (int rr = 0; rr < 4; rr++) {
            const int n = ty + 16*rr;
            const int i = n >> 3, j = n & 7;
            const int h1 = (wh*8 + i + SHIFT) & 255;
            const int w1 = (ww*8 + j + SHIFT) & 255;
            const size_t base = (((size_t)b*HH + h1)*WW2 + w1)*CDIM;
#pragma unroll
            for (int cc = 0; cc < 6; cc++) {
                const int c = tx + 16*cc;
                g_x1[base + c] = x[base + c] + acc[rr][cc] + pb[c];
            }
        }
    }
}

// ---------------------------------------------------------------------------
// Kernel 2: 128 pixels/block  LN2 + MLP (96->384 GELU 384->96) + residual
// Chunk-fused: per 64 hidden cols, GEMM1+GELU -> smem chunk -> partial GEMM2
// into persistent register accumulators. Weights staged through smem.
// ---------------------------------------------------------------------------
__global__ __launch_bounds__(256, 1) void k_mlp(
    const float* __restrict__ n2g, const float* __restrict__ n2b,
    const float* __restrict__ w1,  const float* __restrict__ b1,
    const float* __restrict__ w2,  const float* __restrict__ b2,
    float* __restrict__ out)
{
    extern __shared__ float sm[];
    float* sx  = sm;                       // MROWS x 96  raw x1 (residual)
    float* sn  = sx  + MROWS*SXS;          // MROWS x 100 LN'd
    float* st  = sn  + MROWS*SNS;          // MROWS x 68  hidden chunk (GELU'd)
    float* sw1 = st  + MROWS*STS;          // 96 x 64     staged w1 chunk
    float* sw2 = sw1 + 96*SW1S;            // 64 x 96     staged w2 chunk

    const int t  = threadIdx.x;
    const size_t p0 = (size_t)blockIdx.x * MROWS;

    // load 128 consecutive pixels (float4)
    {
        const float4* src = (const float4*)(g_x1 + p0*CDIM);
        float4* dst = (float4*)sx;
        for (int e = t; e < MROWS*CDIM/4; e += 256) dst[e] = src[e];
    }
    __syncthreads();

    // LN2: 2 lanes per row, 48 contiguous cols each
    {
        const int n = t >> 1, q = t & 1;
        const float* row = sx + n*SXS + q*48;
        float s1 = 0.f, s2 = 0.f;
#pragma unroll
        for (int k = 0; k < 12; k++) {
            float4 v = ((const float4*)row)[k];
            s1 += v.x+v.y+v.z+v.w;
            s2 += v.x*v.x+v.y*v.y+v.z*v.z+v.w*v.w;
        }
        s1 += __shfl_xor_sync(0xffffffffu, s1, 1);
        s2 += __shfl_xor_sync(0xffffffffu, s2, 1);
        const float mean = s1 * (1.f/96.f);
        const float var  = s2 * (1.f/96.f) - mean*mean;
        const float rstd = rsqrtf(var + 1e-5f);
        float* drow = sn + n*SNS + q*48;
        const float4* gg = (const float4*)(n2g + q*48);
        const float4* bb = (const float4*)(n2b + q*48);
#pragma unroll
        for (int k = 0; k < 12; k++) {
            float4 v = ((const float4*)row)[k];
            float4 g = gg[k], b = bb[k], o;
            o.x = (v.x-mean)*rstd*g.x + b.x;
            o.y = (v.y-mean)*rstd*g.y + b.y;
            o.z = (v.z-mean)*rstd*g.z + b.z;
            o.w = (v.w-mean)*rstd*g.w + b.w;
            ((float4*)drow)[k] = o;
        }
    }
    __syncthreads();

    const int tx = t & 15, ty = t >> 4;

    // persistent output accumulators: 8 rows x 6 cols per thread
    float acc2[8][6];
#pragma unroll
    for (int rr = 0; rr < 8; rr++)
#pragma unroll
        for (int cc = 0; cc < 6; cc++) acc2[rr][cc] = 0.f;

    for (int chunk = 0; chunk < 6; chunk++) {
        const int co0 = chunk * 64;

        // stage w1 chunk (96 x 64) and w2 chunk (64 x 96), float4
        {
            float4* d1 = (float4*)sw1;
            for (int e = t; e < 96*64/4; e += 256) {
                const int ci = e >> 4, c4 = e & 15;
                const float4* s1p = (const float4*)(w1 + ci*384 + co0);
                d1[ci*16 + c4] = s1p[c4];
            }
            float4* d2 = (float4*)sw2;
            const float4* s2p = (const float4*)(w2 + co0*96);
            for (int e = t; e < 64*96/4; e += 256) d2[e] = s2p[e];
        }
        __syncthreads();

        // GEMM1: (128x96)@(96x64) + b1, GELU -> st
        {
            float acc1[8][4];
#pragma unroll
            for (int rr = 0; rr < 8; rr++)
#pragma unroll
                for (int cc = 0; cc < 4; cc++) acc1[rr][cc] = 0.f;

            for (int ci = 0; ci < 96; ci += 4) {
                float4 a4[8], w4[4];
#pragma unroll
                for (int rr = 0; rr < 8; rr++)
                    a4[rr] = *(const float4*)(sn + (ty + 16*rr)*SNS + ci);
#pragma unroll
                for (int j = 0; j < 4; j++)
                    w4[j] = *(const float4*)(sw1 + (ci + j)*SW1S + tx*4);
#pragma unroll
                for (int rr = 0; rr < 8; rr++) {
#pragma unroll
                    for (int j = 0; j < 4; j++) {
                        const float av = (j==0)?a4[rr].x:(j==1)?a4[rr].y:(j==2)?a4[rr].z:a4[rr].w;
                        acc1[rr][0] = fmaf(av, w4[j].x, acc1[rr][0]);
                        acc1[rr][1] = fmaf(av, w4[j].y, acc1[rr][1]);
                        acc1[rr][2] = fmaf(av, w4[j].z, acc1[rr][2]);
                        acc1[rr][3] = fmaf(av, w4[j].w, acc1[rr][3]);
                    }
                }
            }
            const float4 b1v = *(const float4*)(b1 + co0 + tx*4);
#pragma unroll
            for (int rr = 0; rr < 8; rr++) {
                float v0 = acc1[rr][0] + b1v.x;
                float v1 = acc1[rr][1] + b1v.y;
                float v2 = acc1[rr][2] + b1v.z;
                float v3 = acc1[rr][3] + b1v.w;
                v0 = 0.5f*v0*(1.f + erff(v0*0.7071067811865476f));
                v1 = 0.5f*v1*(1.f + erff(v1*0.7071067811865476f));
                v2 = 0.5f*v2*(1.f + erff(v2*0.7071067811865476f));
                v3 = 0.5f*v3*(1.f + erff(v3*0.7071067811865476f));
                float4 o4 = make_float4(v0, v1, v2, v3);
                *(float4*)(st + (ty + 16*rr)*STS + tx*4) = o4;
            }
        }
        __syncthreads();

        // GEMM2 partial: (128x64)@(64x96) accumulated into acc2
        for (int k = 0; k < 64; k++) {
            float a[8], w[6];
#pragma unroll
            for (int rr = 0; rr < 8; rr++) a[rr] = st[(ty + 16*rr)*STS + k];
#pragma unroll
            for (int cc = 0; cc < 6; cc++) w[cc] = sw2[k*SW2S + tx + 16*cc];
#pragma unroll
            for (int rr = 0; rr < 8; rr++)
#pragma unroll
                for (int cc = 0; cc < 6; cc++) acc2[rr][cc] = fmaf(a[rr], w[cc], acc2[rr][cc]);
        }
        __syncthreads();
    }

    // store: out = x1 + mlp + b2
#pragma unroll
    for (int cc = 0; cc < 6; cc++) {
        const int c = tx + 16*cc;
        const float b2v = b2[c];
#pragma unroll
        for (int rr = 0; rr < 8; rr++) {
            const int r = ty + 16*rr;
            out[(p0 + r)*CDIM + c] = sx[r*SXS + c] + acc2[rr][cc] + b2v;
        }
    }
}

// ---------------------------------------------------------------------------
extern "C" void kernel_launch(void* const* d_in, const int* in_sizes, int n_in,
                              void* d_out, int out_size)
{
    const float* x    = (const float*)d_in[0];
    const float* n1g  = (const float*)d_in[1];
    const float* n1b  = (const float*)d_in[2];
    const float* qkvw = (const float*)d_in[3];
    const float* qkvb = (const float*)d_in[4];
    const float* relb = (const float*)d_in[5];
    const float* pw   = (const float*)d_in[6];
    const float* pb   = (const float*)d_in[7];
    const float* n2g  = (const float*)d_in[8];
    const float* n2b  = (const float*)d_in[9];
    const float* w1   = (const float*)d_in[10];
    const float* b1   = (const float*)d_in[11];
    const float* w2   = (const float*)d_in[12];
    const float* b2   = (const float*)d_in[13];
    float* out = (float*)d_out;

    cudaFuncSetAttribute(k_attn, cudaFuncAttributeMaxDynamicSharedMemorySize, SMEM1);
    cudaFuncSetAttribute(k_mlp,  cudaFuncAttributeMaxDynamicSharedMemorySize, SMEM2);

    k_attn<<<NWIN, 256, SMEM1>>>(x, n1g, n1b, qkvw, qkvb, relb, pw, pb);
    k_mlp<<<NPIX/MROWS, 256, SMEM2>>>(n2g, n2b, w1, b1, w2, b2, out);
}